// round 1
// baseline (speedup 1.0000x reference)
#include <cuda_runtime.h>
#include <cuda_bf16.h>
#include <cstdint>

// Problem constants
#define DM     256          // d_model
#define HW     3136         // 56*56 pixels per batch
#define NB     2            // batch
#define PTOT   (NB*HW)      // 6272 total pixels
#define NH     8            // heads
#define HD     32           // head dim
#define WS     7            // window
#define NW     49           // window^2

// Scratch (device globals; allocation is forbidden). Layout: pixel-major [P, 256].
__device__ float g_q[PTOT * DM];
__device__ float g_k[PTOT * DM];
__device__ float g_v[PTOT * DM];
__device__ float g_a[PTOT * DM];

// ---------------------------------------------------------------------------
// Fused QKV projection GEMM.
// out[p][o] = sum_c W[o][c] * x[b][c][p] + bias[o]
// grid: (HW/64, DM/64, NB*3)   block: 256 threads, 64x64 tile, BK=16, 4x4/thr
// ---------------------------------------------------------------------------
__global__ __launch_bounds__(256) void qkv_gemm_kernel(
    const float* __restrict__ x,
    const float* __restrict__ wq, const float* __restrict__ bq,
    const float* __restrict__ wk, const float* __restrict__ bk,
    const float* __restrict__ wv, const float* __restrict__ bv)
{
    const int bz = blockIdx.z;
    const int b  = bz / 3;
    const int m  = bz - b * 3;
    const float* __restrict__ W    = (m == 0) ? wq : (m == 1) ? wk : wv;
    const float* __restrict__ bias = (m == 0) ? bq : (m == 1) ? bk : bv;
    float* __restrict__ out        = (m == 0) ? g_q : (m == 1) ? g_k : g_v;

    const int p0 = blockIdx.x * 64;   // pixel tile origin
    const int n0 = blockIdx.y * 64;   // out-channel tile origin

    __shared__ __align__(16) float Ws[16][64];   // [c][o]
    __shared__ __align__(16) float Xs[16][64];   // [c][p]

    const int tid = threadIdx.x;
    const int tx  = tid & 15;         // pixel micro index (x4)
    const int ty  = tid >> 4;         // out-channel micro index (x4)

    float acc[4][4] = {};

    const float* __restrict__ xb = x + (size_t)b * DM * HW;

    for (int k0 = 0; k0 < DM; k0 += 16) {
        // Load weight tile: 64 o x 16 c
        {
            const int o  = tid >> 2;            // 0..63
            const int c0 = (tid & 3) * 4;       // 0,4,8,12
            float4 w4 = *(const float4*)(W + (size_t)(n0 + o) * DM + k0 + c0);
            Ws[c0 + 0][o] = w4.x;
            Ws[c0 + 1][o] = w4.y;
            Ws[c0 + 2][o] = w4.z;
            Ws[c0 + 3][o] = w4.w;
        }
        // Load x tile: 16 c x 64 p (coalesced along p)
        {
            const int c  = tid >> 4;            // 0..15
            const int pp = (tid & 15) * 4;      // 0..60
            float4 x4 = *(const float4*)(xb + (size_t)(k0 + c) * HW + p0 + pp);
            *(float4*)&Xs[c][pp] = x4;
        }
        __syncthreads();
        #pragma unroll
        for (int kk = 0; kk < 16; kk++) {
            float4 xv = *(const float4*)&Xs[kk][tx * 4];
            float4 wv = *(const float4*)&Ws[kk][ty * 4];
            float wa[4] = {wv.x, wv.y, wv.z, wv.w};
            float xa[4] = {xv.x, xv.y, xv.z, xv.w};
            #pragma unroll
            for (int i = 0; i < 4; i++)
                #pragma unroll
                for (int j = 0; j < 4; j++)
                    acc[i][j] = fmaf(wa[i], xa[j], acc[i][j]);
        }
        __syncthreads();
    }

    const float b0 = bias[n0 + ty * 4 + 0];
    const float b1 = bias[n0 + ty * 4 + 1];
    const float b2 = bias[n0 + ty * 4 + 2];
    const float b3 = bias[n0 + ty * 4 + 3];
    #pragma unroll
    for (int j = 0; j < 4; j++) {
        const int p = p0 + tx * 4 + j;
        float4 r;
        r.x = acc[0][j] + b0;
        r.y = acc[1][j] + b1;
        r.z = acc[2][j] + b2;
        r.w = acc[3][j] + b3;
        *(float4*)(out + (size_t)(b * HW + p) * DM + n0 + ty * 4) = r;
    }
}

// ---------------------------------------------------------------------------
// Windowed attention.
// block = one pixel (gridDim.x = PTOT), warp = one head, lane = head dim.
// Zero-padded windows: OOB neighbors get k=0 (score 0, inside softmax), v=0.
// ---------------------------------------------------------------------------
__global__ __launch_bounds__(256) void attn_kernel()
{
    const int p    = blockIdx.x;             // global pixel 0..PTOT-1
    const int b    = p / HW;
    const int rem  = p - b * HW;
    const int y    = rem / 56;
    const int xx   = rem - y * 56;
    const int warp = threadIdx.x >> 5;       // head
    const int lane = threadIdx.x & 31;       // dim
    const int hoff = warp * HD;

    const float scale = 0.17677669529663687f;   // 32^-0.5
    const float qv = g_q[(size_t)p * DM + hoff + lane] * scale;

    float s0 = 0.f, s1 = 0.f;                 // scores n=lane, n=lane+32
    #pragma unroll
    for (int n = 0; n < NW; n++) {
        const int dy = n / WS - 3;
        const int dx = n % WS - 3;
        const int y2 = y + dy;
        const int x2 = xx + dx;
        const bool valid = ((unsigned)y2 < 56u) && ((unsigned)x2 < 56u);
        float kk = 0.f;
        if (valid)
            kk = g_k[((size_t)(b * HW + y2 * 56 + x2)) * DM + hoff + lane];
        float d = qv * kk;
        #pragma unroll
        for (int o = 16; o; o >>= 1)
            d += __shfl_xor_sync(0xffffffffu, d, o);
        if (lane == (n & 31)) { if (n < 32) s0 = d; else s1 = d; }
    }

    // softmax over 49 scores: s0 valid on all lanes (n=0..31), s1 on lanes 0..16
    float mx = (lane < 17) ? fmaxf(s0, s1) : s0;
    #pragma unroll
    for (int o = 16; o; o >>= 1)
        mx = fmaxf(mx, __shfl_xor_sync(0xffffffffu, mx, o));
    const float e0 = __expf(s0 - mx);
    const float e1 = (lane < 17) ? __expf(s1 - mx) : 0.f;
    float sum = e0 + e1;
    #pragma unroll
    for (int o = 16; o; o >>= 1)
        sum += __shfl_xor_sync(0xffffffffu, sum, o);
    const float inv = 1.f / sum;
    const float pr0 = e0 * inv;
    const float pr1 = e1 * inv;

    float acc = 0.f;
    #pragma unroll
    for (int n = 0; n < NW; n++) {
        const float src = (n < 32) ? pr0 : pr1;
        const float pn  = __shfl_sync(0xffffffffu, src, n & 31);
        const int dy = n / WS - 3;
        const int dx = n % WS - 3;
        const int y2 = y + dy;
        const int x2 = xx + dx;
        const bool valid = ((unsigned)y2 < 56u) && ((unsigned)x2 < 56u);
        float vv = 0.f;
        if (valid)
            vv = g_v[((size_t)(b * HW + y2 * 56 + x2)) * DM + hoff + lane];
        acc = fmaf(pn, vv, acc);
    }
    g_a[(size_t)p * DM + hoff + lane] = acc;
}

// ---------------------------------------------------------------------------
// Output projection GEMM.
// out[b][o][p] = sum_c Wo[o][c] * g_a[b*HW+p][c] + bo[o]
// grid: (HW/64, DM/64, NB)   block: 256 threads
// ---------------------------------------------------------------------------
__global__ __launch_bounds__(256) void oproj_gemm_kernel(
    const float* __restrict__ wo, const float* __restrict__ bo,
    float* __restrict__ out)
{
    const int b  = blockIdx.z;
    const int p0 = blockIdx.x * 64;
    const int n0 = blockIdx.y * 64;

    __shared__ __align__(16) float Ws[16][64];   // [c][o]
    __shared__ __align__(16) float Ys[16][64];   // [c][p]

    const int tid = threadIdx.x;
    const int tx  = tid & 15;
    const int ty  = tid >> 4;

    float acc[4][4] = {};
    const float* __restrict__ Y = g_a + (size_t)b * HW * DM;

    for (int k0 = 0; k0 < DM; k0 += 16) {
        {
            const int o  = tid >> 2;
            const int c0 = (tid & 3) * 4;
            float4 w4 = *(const float4*)(wo + (size_t)(n0 + o) * DM + k0 + c0);
            Ws[c0 + 0][o] = w4.x;
            Ws[c0 + 1][o] = w4.y;
            Ws[c0 + 2][o] = w4.z;
            Ws[c0 + 3][o] = w4.w;
        }
        {
            const int pp = tid >> 2;
            const int c0 = (tid & 3) * 4;
            float4 y4 = *(const float4*)(Y + (size_t)(p0 + pp) * DM + k0 + c0);
            Ys[c0 + 0][pp] = y4.x;
            Ys[c0 + 1][pp] = y4.y;
            Ys[c0 + 2][pp] = y4.z;
            Ys[c0 + 3][pp] = y4.w;
        }
        __syncthreads();
        #pragma unroll
        for (int kk = 0; kk < 16; kk++) {
            float4 yv = *(const float4*)&Ys[kk][tx * 4];
            float4 wv = *(const float4*)&Ws[kk][ty * 4];
            float wa[4] = {wv.x, wv.y, wv.z, wv.w};
            float ya[4] = {yv.x, yv.y, yv.z, yv.w};
            #pragma unroll
            for (int i = 0; i < 4; i++)
                #pragma unroll
                for (int j = 0; j < 4; j++)
                    acc[i][j] = fmaf(wa[i], ya[j], acc[i][j]);
        }
        __syncthreads();
    }

    #pragma unroll
    for (int i = 0; i < 4; i++) {
        const int o = n0 + ty * 4 + i;
        const float bb = bo[o];
        float4 r;
        r.x = acc[i][0] + bb;
        r.y = acc[i][1] + bb;
        r.z = acc[i][2] + bb;
        r.w = acc[i][3] + bb;
        *(float4*)(out + ((size_t)b * DM + o) * HW + p0 + tx * 4) = r;
    }
}

// ---------------------------------------------------------------------------
extern "C" void kernel_launch(void* const* d_in, const int* in_sizes, int n_in,
                              void* d_out, int out_size)
{
    (void)in_sizes; (void)n_in; (void)out_size;
    const float* x  = (const float*)d_in[0];
    const float* wq = (const float*)d_in[1];
    const float* bq = (const float*)d_in[2];
    const float* wk = (const float*)d_in[3];
    const float* bk = (const float*)d_in[4];
    const float* wv = (const float*)d_in[5];
    const float* bv = (const float*)d_in[6];
    const float* wo = (const float*)d_in[7];
    const float* bo = (const float*)d_in[8];
    float* out = (float*)d_out;

    qkv_gemm_kernel<<<dim3(HW / 64, DM / 64, NB * 3), 256>>>(x, wq, bq, wk, bk, wv, bv);
    attn_kernel<<<PTOT, 256>>>();
    oproj_gemm_kernel<<<dim3(HW / 64, DM / 64, NB), 256>>>(wo, bo, out);
}

// round 2
// speedup vs baseline: 1.4537x; 1.4537x over previous
#include <cuda_runtime.h>
#include <cuda_bf16.h>
#include <cstdint>

// Problem constants
#define DM     256          // d_model
#define HW     3136         // 56*56 pixels per batch
#define NB     2            // batch
#define PTOT   (NB*HW)      // 6272 total pixels
#define NH     8            // heads
#define HD     32           // head dim
#define WS     7            // window
#define NW     49           // window^2

// Scratch (device globals). Layout: channel-major [b][c][H][W] (c = h*32+d).
__device__ float g_q[PTOT * DM];
__device__ float g_k[PTOT * DM];
__device__ float g_v[PTOT * DM];
__device__ float g_a[PTOT * DM];

// ---------------------------------------------------------------------------
// Fused QKV projection GEMM.
// out[b][o][p] = sum_c W[o][c] * x[b][c][p] + bias[o]   (channel-major out)
// grid: (HW/64, DM/64, NB*3)   block: 256 threads, 64x64 tile, BK=16, 4x4/thr
// ---------------------------------------------------------------------------
__global__ __launch_bounds__(256) void qkv_gemm_kernel(
    const float* __restrict__ x,
    const float* __restrict__ wq, const float* __restrict__ bq,
    const float* __restrict__ wk, const float* __restrict__ bk,
    const float* __restrict__ wv, const float* __restrict__ bv)
{
    const int bz = blockIdx.z;
    const int b  = bz / 3;
    const int m  = bz - b * 3;
    const float* __restrict__ W    = (m == 0) ? wq : (m == 1) ? wk : wv;
    const float* __restrict__ bias = (m == 0) ? bq : (m == 1) ? bk : bv;
    float* __restrict__ out        = (m == 0) ? g_q : (m == 1) ? g_k : g_v;

    const int p0 = blockIdx.x * 64;   // pixel tile origin
    const int n0 = blockIdx.y * 64;   // out-channel tile origin

    __shared__ __align__(16) float Ws[16][64];   // [c][o]
    __shared__ __align__(16) float Xs[16][64];   // [c][p]

    const int tid = threadIdx.x;
    const int tx  = tid & 15;         // pixel micro index (x4)
    const int ty  = tid >> 4;         // out-channel micro index (x4)

    float acc[4][4] = {};

    const float* __restrict__ xb = x + (size_t)b * DM * HW;

    for (int k0 = 0; k0 < DM; k0 += 16) {
        {
            const int o  = tid >> 2;            // 0..63
            const int c0 = (tid & 3) * 4;       // 0,4,8,12
            float4 w4 = *(const float4*)(W + (size_t)(n0 + o) * DM + k0 + c0);
            Ws[c0 + 0][o] = w4.x;
            Ws[c0 + 1][o] = w4.y;
            Ws[c0 + 2][o] = w4.z;
            Ws[c0 + 3][o] = w4.w;
        }
        {
            const int c  = tid >> 4;            // 0..15
            const int pp = (tid & 15) * 4;      // 0..60
            float4 x4 = *(const float4*)(xb + (size_t)(k0 + c) * HW + p0 + pp);
            *(float4*)&Xs[c][pp] = x4;
        }
        __syncthreads();
        #pragma unroll
        for (int kk = 0; kk < 16; kk++) {
            float4 xv = *(const float4*)&Xs[kk][tx * 4];
            float4 wv = *(const float4*)&Ws[kk][ty * 4];
            float wa[4] = {wv.x, wv.y, wv.z, wv.w};
            float xa[4] = {xv.x, xv.y, xv.z, xv.w};
            #pragma unroll
            for (int i = 0; i < 4; i++)
                #pragma unroll
                for (int j = 0; j < 4; j++)
                    acc[i][j] = fmaf(wa[i], xa[j], acc[i][j]);
        }
        __syncthreads();
    }

    // Channel-major write: out[(b*DM + o)*HW + p], coalesced float4 along p.
    #pragma unroll
    for (int i = 0; i < 4; i++) {
        const int o = n0 + ty * 4 + i;
        const float bb = bias[o];
        float4 r;
        r.x = acc[i][0] + bb;
        r.y = acc[i][1] + bb;
        r.z = acc[i][2] + bb;
        r.w = acc[i][3] + bb;
        *(float4*)(out + ((size_t)b * DM + o) * HW + p0 + tx * 4) = r;
    }
}

// ---------------------------------------------------------------------------
// Windowed attention, stencil style.
// grid: (1, 7, NB*NH). Block = 224 threads = 8 rows x 28 col-pairs.
// Thread handles 2 adjacent pixels (x0, x0+1). Scores in 98 registers.
// K/V slices (one d at a time) double-buffered in smem with halo, zero-padded.
// ---------------------------------------------------------------------------
__device__ __forceinline__ void load_slice(float* dst, const float* __restrict__ src,
                                           int y0, int tid)
{
    // 14 rows x 64 cols; global row = y0-3+row, global col = col-3; OOB -> 0.
    #pragma unroll
    for (int it = 0; it < 4; it++) {
        int idx = tid + it * 224;
        int row = idx >> 6;
        int col = idx & 63;
        int gy = y0 - 3 + row;
        int gx = col - 3;
        float v = 0.f;
        if (((unsigned)gy < 56u) && ((unsigned)gx < 56u))
            v = src[gy * 56 + gx];
        dst[idx] = v;
    }
}

__global__ __launch_bounds__(224, 1) void attn_kernel()
{
    const int bh  = blockIdx.z;           // b*NH + h
    const int y0  = blockIdx.y * 8;
    const int tid = threadIdx.x;          // 0..223
    const int r   = tid / 28;             // 0..7 (row in tile)
    const int xp  = tid - r * 28;
    const int x0  = xp * 2;
    const int y   = y0 + r;
    const int p   = y * 56 + x0;

    const float* __restrict__ qbase = g_q + (size_t)bh * HD * HW;
    const float* __restrict__ kbase = g_k + (size_t)bh * HD * HW;
    const float* __restrict__ vbase = g_v + (size_t)bh * HD * HW;
    float*       __restrict__ abase = g_a + (size_t)bh * HD * HW;

    __shared__ __align__(16) float sk[2][14][64];

    const float scale = 0.17677669529663687f;  // 32^-0.5

    float s0[NW], s1[NW];
    #pragma unroll
    for (int i = 0; i < NW; i++) { s0[i] = 0.f; s1[i] = 0.f; }

    // ---- Phase 1: scores ----
    load_slice(&sk[0][0][0], kbase, y0, tid);
    __syncthreads();

    for (int d = 0; d < HD; d++) {
        const int cur = d & 1;
        if (d + 1 < HD)
            load_slice(&sk[cur ^ 1][0][0], kbase + (size_t)(d + 1) * HW, y0, tid);

        float2 q2 = *(const float2*)(qbase + (size_t)d * HW + p);
        const float q0 = q2.x * scale;
        const float q1 = q2.y * scale;

        #pragma unroll
        for (int dy = 0; dy < WS; dy++) {
            float kv[8];
            #pragma unroll
            for (int i = 0; i < 4; i++) {
                float2 t = *(const float2*)&sk[cur][r + dy][x0 + 2 * i];
                kv[2 * i]     = t.x;
                kv[2 * i + 1] = t.y;
            }
            #pragma unroll
            for (int dx = 0; dx < WS; dx++) {
                s0[dy * WS + dx] = fmaf(q0, kv[dx],     s0[dy * WS + dx]);
                s1[dy * WS + dx] = fmaf(q1, kv[dx + 1], s1[dy * WS + dx]);
            }
        }
        __syncthreads();
    }

    // ---- Softmax over 49 scores (zero scores from padding participate) ----
    {
        float mx0 = s0[0], mx1 = s1[0];
        #pragma unroll
        for (int i = 1; i < NW; i++) { mx0 = fmaxf(mx0, s0[i]); mx1 = fmaxf(mx1, s1[i]); }
        float sum0 = 0.f, sum1 = 0.f;
        #pragma unroll
        for (int i = 0; i < NW; i++) {
            s0[i] = __expf(s0[i] - mx0); sum0 += s0[i];
            s1[i] = __expf(s1[i] - mx1); sum1 += s1[i];
        }
        const float inv0 = 1.f / sum0;
        const float inv1 = 1.f / sum1;
        #pragma unroll
        for (int i = 0; i < NW; i++) { s0[i] *= inv0; s1[i] *= inv1; }
    }

    // ---- Phase 2: output accumulation over v ----
    load_slice(&sk[0][0][0], vbase, y0, tid);
    __syncthreads();

    for (int d = 0; d < HD; d++) {
        const int cur = d & 1;
        if (d + 1 < HD)
            load_slice(&sk[cur ^ 1][0][0], vbase + (size_t)(d + 1) * HW, y0, tid);

        float a0 = 0.f, a1 = 0.f;
        #pragma unroll
        for (int dy = 0; dy < WS; dy++) {
            float kv[8];
            #pragma unroll
            for (int i = 0; i < 4; i++) {
                float2 t = *(const float2*)&sk[cur][r + dy][x0 + 2 * i];
                kv[2 * i]     = t.x;
                kv[2 * i + 1] = t.y;
            }
            #pragma unroll
            for (int dx = 0; dx < WS; dx++) {
                a0 = fmaf(s0[dy * WS + dx], kv[dx],     a0);
                a1 = fmaf(s1[dy * WS + dx], kv[dx + 1], a1);
            }
        }
        float2 o2 = make_float2(a0, a1);
        *(float2*)(abase + (size_t)d * HW + p) = o2;
        __syncthreads();
    }
}

// ---------------------------------------------------------------------------
// Output projection GEMM.
// out[b][o][p] = sum_c Wo[o][c] * g_a[b][c][p] + bo[o]
// grid: (HW/64, DM/64, NB)   block: 256 threads
// ---------------------------------------------------------------------------
__global__ __launch_bounds__(256) void oproj_gemm_kernel(
    const float* __restrict__ wo, const float* __restrict__ bo,
    float* __restrict__ out)
{
    const int b  = blockIdx.z;
    const int p0 = blockIdx.x * 64;
    const int n0 = blockIdx.y * 64;

    __shared__ __align__(16) float Ws[16][64];   // [c][o]
    __shared__ __align__(16) float Ys[16][64];   // [c][p]

    const int tid = threadIdx.x;
    const int tx  = tid & 15;
    const int ty  = tid >> 4;

    float acc[4][4] = {};
    const float* __restrict__ Y = g_a + (size_t)b * DM * HW;

    for (int k0 = 0; k0 < DM; k0 += 16) {
        {
            const int o  = tid >> 2;
            const int c0 = (tid & 3) * 4;
            float4 w4 = *(const float4*)(wo + (size_t)(n0 + o) * DM + k0 + c0);
            Ws[c0 + 0][o] = w4.x;
            Ws[c0 + 1][o] = w4.y;
            Ws[c0 + 2][o] = w4.z;
            Ws[c0 + 3][o] = w4.w;
        }
        {
            const int c  = tid >> 4;            // 0..15
            const int pp = (tid & 15) * 4;      // 0..60
            float4 y4 = *(const float4*)(Y + (size_t)(k0 + c) * HW + p0 + pp);
            *(float4*)&Ys[c][pp] = y4;
        }
        __syncthreads();
        #pragma unroll
        for (int kk = 0; kk < 16; kk++) {
            float4 yv = *(const float4*)&Ys[kk][tx * 4];
            float4 wv = *(const float4*)&Ws[kk][ty * 4];
            float wa[4] = {wv.x, wv.y, wv.z, wv.w};
            float ya[4] = {yv.x, yv.y, yv.z, yv.w};
            #pragma unroll
            for (int i = 0; i < 4; i++)
                #pragma unroll
                for (int j = 0; j < 4; j++)
                    acc[i][j] = fmaf(wa[i], ya[j], acc[i][j]);
        }
        __syncthreads();
    }

    #pragma unroll
    for (int i = 0; i < 4; i++) {
        const int o = n0 + ty * 4 + i;
        const float bb = bo[o];
        float4 r;
        r.x = acc[i][0] + bb;
        r.y = acc[i][1] + bb;
        r.z = acc[i][2] + bb;
        r.w = acc[i][3] + bb;
        *(float4*)(out + ((size_t)b * DM + o) * HW + p0 + tx * 4) = r;
    }
}

// ---------------------------------------------------------------------------
extern "C" void kernel_launch(void* const* d_in, const int* in_sizes, int n_in,
                              void* d_out, int out_size)
{
    (void)in_sizes; (void)n_in; (void)out_size;
    const float* x  = (const float*)d_in[0];
    const float* wq = (const float*)d_in[1];
    const float* bq = (const float*)d_in[2];
    const float* wk = (const float*)d_in[3];
    const float* bk = (const float*)d_in[4];
    const float* wv = (const float*)d_in[5];
    const float* bv = (const float*)d_in[6];
    const float* wo = (const float*)d_in[7];
    const float* bo = (const float*)d_in[8];
    float* out = (float*)d_out;

    qkv_gemm_kernel<<<dim3(HW / 64, DM / 64, NB * 3), 256>>>(x, wq, bq, wk, bk, wv, bv);
    attn_kernel<<<dim3(1, 7, NB * NH), 224>>>();
    oproj_gemm_kernel<<<dim3(HW / 64, DM / 64, NB), 256>>>(wo, bo, out);
}

// round 3
// speedup vs baseline: 1.5854x; 1.0906x over previous
#include <cuda_runtime.h>
#include <cuda_bf16.h>
#include <cstdint>

// Problem constants
#define DM     256
#define HW     3136
#define NB     2
#define PTOT   (NB*HW)
#define NH     8
#define HD     32
#define WS     7
#define NW     49

// Scratch (device globals). Layout: channel-major [b][c][H][W] (c = h*32+d).
__device__ float g_q[PTOT * DM];
__device__ float g_k[PTOT * DM];
__device__ float g_v[PTOT * DM];
__device__ float g_a[PTOT * DM];

// ---- packed f32x2 helpers (FFMA2 path; ptxas never auto-fuses) -----------
typedef unsigned long long u64;
__device__ __forceinline__ u64 pack2s(float v) {
    u64 r; asm("mov.b64 %0, {%1, %1};" : "=l"(r) : "f"(v)); return r;
}
__device__ __forceinline__ void ffma2(u64& d, u64 a, u64 b) {
    asm("fma.rn.f32x2 %0, %1, %2, %0;" : "+l"(d) : "l"(a), "l"(b));
}
__device__ __forceinline__ float2 unpack2(u64 v) {
    float2 r; asm("mov.b64 {%0, %1}, %2;" : "=f"(r.x), "=f"(r.y) : "l"(v)); return r;
}

// ---------------------------------------------------------------------------
// Fused QKV projection GEMM (f32x2 inner product).
// out[b][o][p] = sum_c W[o][c] * x[b][c][p] + bias[o]   (channel-major out)
// grid: (HW/64, DM/64, NB*3)   block: 256, 64x64 tile, BK=16, 4x4/thr
// ---------------------------------------------------------------------------
__global__ __launch_bounds__(256) void qkv_gemm_kernel(
    const float* __restrict__ x,
    const float* __restrict__ wq, const float* __restrict__ bq,
    const float* __restrict__ wk, const float* __restrict__ bk,
    const float* __restrict__ wv, const float* __restrict__ bv)
{
    const int bz = blockIdx.z;
    const int b  = bz / 3;
    const int m  = bz - b * 3;
    const float* __restrict__ W    = (m == 0) ? wq : (m == 1) ? wk : wv;
    const float* __restrict__ bias = (m == 0) ? bq : (m == 1) ? bk : bv;
    float* __restrict__ out        = (m == 0) ? g_q : (m == 1) ? g_k : g_v;

    const int p0 = blockIdx.x * 64;
    const int n0 = blockIdx.y * 64;

    __shared__ __align__(16) float Ws[16][64];
    __shared__ __align__(16) float Xs[16][64];

    const int tid = threadIdx.x;
    const int tx  = tid & 15;
    const int ty  = tid >> 4;

    u64 acc2[4][2];
    #pragma unroll
    for (int i = 0; i < 4; i++) { acc2[i][0] = 0ull; acc2[i][1] = 0ull; }

    const float* __restrict__ xb = x + (size_t)b * DM * HW;

    for (int k0 = 0; k0 < DM; k0 += 16) {
        {
            const int o  = tid >> 2;
            const int c0 = (tid & 3) * 4;
            float4 w4 = *(const float4*)(W + (size_t)(n0 + o) * DM + k0 + c0);
            Ws[c0 + 0][o] = w4.x;
            Ws[c0 + 1][o] = w4.y;
            Ws[c0 + 2][o] = w4.z;
            Ws[c0 + 3][o] = w4.w;
        }
        {
            const int c  = tid >> 4;
            const int pp = (tid & 15) * 4;
            float4 x4 = *(const float4*)(xb + (size_t)(k0 + c) * HW + p0 + pp);
            *(float4*)&Xs[c][pp] = x4;
        }
        __syncthreads();
        #pragma unroll
        for (int kk = 0; kk < 16; kk++) {
            ulonglong2 xp = *(const ulonglong2*)&Xs[kk][tx * 4];
            float4 wv4 = *(const float4*)&Ws[kk][ty * 4];
            u64 w0 = pack2s(wv4.x);
            u64 w1 = pack2s(wv4.y);
            u64 w2 = pack2s(wv4.z);
            u64 w3 = pack2s(wv4.w);
            ffma2(acc2[0][0], w0, xp.x); ffma2(acc2[0][1], w0, xp.y);
            ffma2(acc2[1][0], w1, xp.x); ffma2(acc2[1][1], w1, xp.y);
            ffma2(acc2[2][0], w2, xp.x); ffma2(acc2[2][1], w2, xp.y);
            ffma2(acc2[3][0], w3, xp.x); ffma2(acc2[3][1], w3, xp.y);
        }
        __syncthreads();
    }

    #pragma unroll
    for (int i = 0; i < 4; i++) {
        const int o = n0 + ty * 4 + i;
        const float bb = bias[o];
        float2 lo = unpack2(acc2[i][0]);
        float2 hi = unpack2(acc2[i][1]);
        float4 r;
        r.x = lo.x + bb; r.y = lo.y + bb; r.z = hi.x + bb; r.w = hi.y + bb;
        *(float4*)(out + ((size_t)b * DM + o) * HW + p0 + tx * 4) = r;
    }
}

// ---------------------------------------------------------------------------
// Windowed attention, stencil style, 2 d-slices per iteration.
// grid: (1, 7, NB*NH). Block = 224 threads = 8 rows x 28 col-pairs.
// ---------------------------------------------------------------------------
__device__ __forceinline__ void load_slice(float* dst, const float* __restrict__ src,
                                           int y0, int tid)
{
    #pragma unroll
    for (int it = 0; it < 4; it++) {
        int idx = tid + it * 224;
        int row = idx >> 6;
        int col = idx & 63;
        int gy = y0 - 3 + row;
        int gx = col - 3;
        float v = 0.f;
        if (((unsigned)gy < 56u) && ((unsigned)gx < 56u))
            v = src[gy * 56 + gx];
        dst[idx] = v;
    }
}

__global__ __launch_bounds__(224, 1) void attn_kernel()
{
    const int bh  = blockIdx.z;
    const int y0  = blockIdx.y * 8;
    const int tid = threadIdx.x;
    const int r   = tid / 28;
    const int xp  = tid - r * 28;
    const int x0  = xp * 2;
    const int p   = (y0 + r) * 56 + x0;

    const float* __restrict__ qbase = g_q + (size_t)bh * HD * HW;
    const float* __restrict__ kbase = g_k + (size_t)bh * HD * HW;
    const float* __restrict__ vbase = g_v + (size_t)bh * HD * HW;
    float*       __restrict__ abase = g_a + (size_t)bh * HD * HW;

    // [buf][slice][14*64]
    __shared__ __align__(16) float sk[2][2][14 * 64];

    const float scale = 0.17677669529663687f;

    float s0[NW], s1[NW];
    #pragma unroll
    for (int i = 0; i < NW; i++) { s0[i] = 0.f; s1[i] = 0.f; }

    // ---- Phase 1: scores ----
    load_slice(sk[0][0], kbase, y0, tid);
    load_slice(sk[0][1], kbase + HW, y0, tid);
    __syncthreads();

    for (int d = 0; d < HD; d += 2) {
        const int buf = (d >> 1) & 1;
        if (d + 2 < HD) {
            load_slice(sk[buf ^ 1][0], kbase + (size_t)(d + 2) * HW, y0, tid);
            load_slice(sk[buf ^ 1][1], kbase + (size_t)(d + 3) * HW, y0, tid);
        }
        float2 qa = *(const float2*)(qbase + (size_t)d * HW + p);
        float2 qb = *(const float2*)(qbase + (size_t)(d + 1) * HW + p);
        const float qa0 = qa.x * scale, qa1 = qa.y * scale;
        const float qb0 = qb.x * scale, qb1 = qb.y * scale;

        #pragma unroll
        for (int dy = 0; dy < WS; dy++) {
            float ka[8], kb[8];
            #pragma unroll
            for (int i = 0; i < 4; i++) {
                float2 ta = *(const float2*)&sk[buf][0][(r + dy) * 64 + x0 + 2 * i];
                float2 tb = *(const float2*)&sk[buf][1][(r + dy) * 64 + x0 + 2 * i];
                ka[2*i] = ta.x; ka[2*i+1] = ta.y;
                kb[2*i] = tb.x; kb[2*i+1] = tb.y;
            }
            #pragma unroll
            for (int dx = 0; dx < WS; dx++) {
                float sa0 = fmaf(qa0, ka[dx],     s0[dy * WS + dx]);
                float sa1 = fmaf(qa1, ka[dx + 1], s1[dy * WS + dx]);
                s0[dy * WS + dx] = fmaf(qb0, kb[dx],     sa0);
                s1[dy * WS + dx] = fmaf(qb1, kb[dx + 1], sa1);
            }
        }
        __syncthreads();
    }

    // ---- Softmax ----
    {
        float mx0 = s0[0], mx1 = s1[0];
        #pragma unroll
        for (int i = 1; i < NW; i++) { mx0 = fmaxf(mx0, s0[i]); mx1 = fmaxf(mx1, s1[i]); }
        float sum0 = 0.f, sum1 = 0.f;
        #pragma unroll
        for (int i = 0; i < NW; i++) {
            s0[i] = __expf(s0[i] - mx0); sum0 += s0[i];
            s1[i] = __expf(s1[i] - mx1); sum1 += s1[i];
        }
        const float inv0 = 1.f / sum0;
        const float inv1 = 1.f / sum1;
        #pragma unroll
        for (int i = 0; i < NW; i++) { s0[i] *= inv0; s1[i] *= inv1; }
    }

    // ---- Phase 2: output ----
    load_slice(sk[0][0], vbase, y0, tid);
    load_slice(sk[0][1], vbase + HW, y0, tid);
    __syncthreads();

    for (int d = 0; d < HD; d += 2) {
        const int buf = (d >> 1) & 1;
        if (d + 2 < HD) {
            load_slice(sk[buf ^ 1][0], vbase + (size_t)(d + 2) * HW, y0, tid);
            load_slice(sk[buf ^ 1][1], vbase + (size_t)(d + 3) * HW, y0, tid);
        }
        float a0 = 0.f, a1 = 0.f, b0 = 0.f, b1 = 0.f;
        #pragma unroll
        for (int dy = 0; dy < WS; dy++) {
            float ka[8], kb[8];
            #pragma unroll
            for (int i = 0; i < 4; i++) {
                float2 ta = *(const float2*)&sk[buf][0][(r + dy) * 64 + x0 + 2 * i];
                float2 tb = *(const float2*)&sk[buf][1][(r + dy) * 64 + x0 + 2 * i];
                ka[2*i] = ta.x; ka[2*i+1] = ta.y;
                kb[2*i] = tb.x; kb[2*i+1] = tb.y;
            }
            #pragma unroll
            for (int dx = 0; dx < WS; dx++) {
                a0 = fmaf(s0[dy * WS + dx], ka[dx],     a0);
                a1 = fmaf(s1[dy * WS + dx], ka[dx + 1], a1);
                b0 = fmaf(s0[dy * WS + dx], kb[dx],     b0);
                b1 = fmaf(s1[dy * WS + dx], kb[dx + 1], b1);
            }
        }
        *(float2*)(abase + (size_t)d * HW + p)       = make_float2(a0, a1);
        *(float2*)(abase + (size_t)(d + 1) * HW + p) = make_float2(b0, b1);
        __syncthreads();
    }
}

// ---------------------------------------------------------------------------
// Output projection GEMM (f32x2).
// ---------------------------------------------------------------------------
__global__ __launch_bounds__(256) void oproj_gemm_kernel(
    const float* __restrict__ wo, const float* __restrict__ bo,
    float* __restrict__ out)
{
    const int b  = blockIdx.z;
    const int p0 = blockIdx.x * 64;
    const int n0 = blockIdx.y * 64;

    __shared__ __align__(16) float Ws[16][64];
    __shared__ __align__(16) float Ys[16][64];

    const int tid = threadIdx.x;
    const int tx  = tid & 15;
    const int ty  = tid >> 4;

    u64 acc2[4][2];
    #pragma unroll
    for (int i = 0; i < 4; i++) { acc2[i][0] = 0ull; acc2[i][1] = 0ull; }

    const float* __restrict__ Y = g_a + (size_t)b * DM * HW;

    for (int k0 = 0; k0 < DM; k0 += 16) {
        {
            const int o  = tid >> 2;
            const int c0 = (tid & 3) * 4;
            float4 w4 = *(const float4*)(wo + (size_t)(n0 + o) * DM + k0 + c0);
            Ws[c0 + 0][o] = w4.x;
            Ws[c0 + 1][o] = w4.y;
            Ws[c0 + 2][o] = w4.z;
            Ws[c0 + 3][o] = w4.w;
        }
        {
            const int c  = tid >> 4;
            const int pp = (tid & 15) * 4;
            float4 y4 = *(const float4*)(Y + (size_t)(k0 + c) * HW + p0 + pp);
            *(float4*)&Ys[c][pp] = y4;
        }
        __syncthreads();
        #pragma unroll
        for (int kk = 0; kk < 16; kk++) {
            ulonglong2 yp = *(const ulonglong2*)&Ys[kk][tx * 4];
            float4 wv4 = *(const float4*)&Ws[kk][ty * 4];
            u64 w0 = pack2s(wv4.x);
            u64 w1 = pack2s(wv4.y);
            u64 w2 = pack2s(wv4.z);
            u64 w3 = pack2s(wv4.w);
            ffma2(acc2[0][0], w0, yp.x); ffma2(acc2[0][1], w0, yp.y);
            ffma2(acc2[1][0], w1, yp.x); ffma2(acc2[1][1], w1, yp.y);
            ffma2(acc2[2][0], w2, yp.x); ffma2(acc2[2][1], w2, yp.y);
            ffma2(acc2[3][0], w3, yp.x); ffma2(acc2[3][1], w3, yp.y);
        }
        __syncthreads();
    }

    #pragma unroll
    for (int i = 0; i < 4; i++) {
        const int o = n0 + ty * 4 + i;
        const float bb = bo[o];
        float2 lo = unpack2(acc2[i][0]);
        float2 hi = unpack2(acc2[i][1]);
        float4 rr;
        rr.x = lo.x + bb; rr.y = lo.y + bb; rr.z = hi.x + bb; rr.w = hi.y + bb;
        *(float4*)(out + ((size_t)b * DM + o) * HW + p0 + tx * 4) = rr;
    }
}

// ---------------------------------------------------------------------------
extern "C" void kernel_launch(void* const* d_in, const int* in_sizes, int n_in,
                              void* d_out, int out_size)
{
    (void)in_sizes; (void)n_in; (void)out_size;
    const float* x  = (const float*)d_in[0];
    const float* wq = (const float*)d_in[1];
    const float* bq = (const float*)d_in[2];
    const float* wk = (const float*)d_in[3];
    const float* bk = (const float*)d_in[4];
    const float* wv = (const float*)d_in[5];
    const float* bv = (const float*)d_in[6];
    const float* wo = (const float*)d_in[7];
    const float* bo = (const float*)d_in[8];
    float* out = (float*)d_out;

    qkv_gemm_kernel<<<dim3(HW / 64, DM / 64, NB * 3), 256>>>(x, wq, bq, wk, bk, wv, bv);
    attn_kernel<<<dim3(1, 7, NB * NH), 224>>>();
    oproj_gemm_kernel<<<dim3(HW / 64, DM / 64, NB), 256>>>(wo, bo, out);
}

// round 4
// speedup vs baseline: 1.7792x; 1.1223x over previous
#include <cuda_runtime.h>
#include <cuda_bf16.h>
#include <cstdint>

// Problem constants
#define DM     256
#define HW     3136
#define NB     2
#define PTOT   (NB*HW)
#define NH     8
#define HD     32
#define WS     7
#define NW     49

// Scratch (device globals). Layout: channel-major [b][c][H][W] (c = h*32+d).
__device__ float g_q[PTOT * DM];
__device__ float g_k[PTOT * DM];
__device__ float g_v[PTOT * DM];
__device__ float g_a[PTOT * DM];

// ---- packed f32x2 helpers ------------------------------------------------
typedef unsigned long long u64;
__device__ __forceinline__ u64 pack2s(float v) {
    u64 r; asm("mov.b64 %0, {%1, %1};" : "=l"(r) : "f"(v)); return r;
}
__device__ __forceinline__ void ffma2(u64& d, u64 a, u64 b) {
    asm("fma.rn.f32x2 %0, %1, %2, %0;" : "+l"(d) : "l"(a), "l"(b));
}
__device__ __forceinline__ float2 unpack2(u64 v) {
    float2 r; asm("mov.b64 {%0, %1}, %2;" : "=f"(r.x), "=f"(r.y) : "l"(v)); return r;
}

#define PXT ((HW + 127) / 128)   // 25 pixel tiles (last partial: 64 px)

// ---------------------------------------------------------------------------
// 128x128x256 GEMM body: out[o][p] = sum_c W[o][c]*X[c][p] + bias[o]
// block 256 thr, 8x8 per thread, BK=16, FFMA2 inner product.
// ---------------------------------------------------------------------------
__device__ __forceinline__ void gemm128(
    const float* __restrict__ W, const float* __restrict__ bias,
    const float* __restrict__ Xb, float* __restrict__ outb,
    int p0, int n0)
{
    __shared__ __align__(16) float Ws[16][128];
    __shared__ __align__(16) float Xs[16][128];

    const int tid = threadIdx.x;
    const int tx  = tid & 15;        // pixel micro (x4, two chunks)
    const int ty  = tid >> 4;        // oc micro (x4, two chunks)

    u64 acc[8][4];
    #pragma unroll
    for (int i = 0; i < 8; i++)
        #pragma unroll
        for (int j = 0; j < 4; j++) acc[i][j] = 0ull;

    const bool xok = (p0 + (tid & 15) * 8 + 7) < HW;

    for (int k0 = 0; k0 < DM; k0 += 16) {
        // W tile -> Ws[c][o] (transpose on store)
        {
            const int o  = tid >> 1;
            const int c0 = (tid & 1) * 8;
            #pragma unroll
            for (int cc = 0; cc < 8; cc += 4) {
                float4 w4 = *(const float4*)(W + (size_t)(n0 + o) * DM + k0 + c0 + cc);
                Ws[c0 + cc + 0][o] = w4.x;
                Ws[c0 + cc + 1][o] = w4.y;
                Ws[c0 + cc + 2][o] = w4.z;
                Ws[c0 + cc + 3][o] = w4.w;
            }
        }
        // X tile -> Xs[c][p] (coalesced), zero-fill OOB pixels
        {
            const int c  = tid >> 4;
            const int px = (tid & 15) * 8;
            if (xok) {
                const float* src = Xb + (size_t)(k0 + c) * HW + p0 + px;
                *(float4*)&Xs[c][px]     = *(const float4*)(src);
                *(float4*)&Xs[c][px + 4] = *(const float4*)(src + 4);
            } else {
                float4 z = make_float4(0.f, 0.f, 0.f, 0.f);
                *(float4*)&Xs[c][px]     = z;
                *(float4*)&Xs[c][px + 4] = z;
            }
        }
        __syncthreads();
        #pragma unroll
        for (int kk = 0; kk < 16; kk++) {
            ulonglong2 xa = *(const ulonglong2*)&Xs[kk][tx * 4];
            ulonglong2 xc = *(const ulonglong2*)&Xs[kk][64 + tx * 4];
            float4 wA = *(const float4*)&Ws[kk][ty * 4];
            float4 wB = *(const float4*)&Ws[kk][64 + ty * 4];
            u64 w[8];
            w[0] = pack2s(wA.x); w[1] = pack2s(wA.y);
            w[2] = pack2s(wA.z); w[3] = pack2s(wA.w);
            w[4] = pack2s(wB.x); w[5] = pack2s(wB.y);
            w[6] = pack2s(wB.z); w[7] = pack2s(wB.w);
            #pragma unroll
            for (int i = 0; i < 8; i++) {
                ffma2(acc[i][0], w[i], xa.x);
                ffma2(acc[i][1], w[i], xa.y);
                ffma2(acc[i][2], w[i], xc.x);
                ffma2(acc[i][3], w[i], xc.y);
            }
        }
        __syncthreads();
    }

    const bool hiok = (p0 + 64 + tx * 4 + 3) < HW;   // second px chunk validity
    #pragma unroll
    for (int i = 0; i < 8; i++) {
        const int o  = n0 + ((i < 4) ? (ty * 4 + i) : (64 + ty * 4 + i - 4));
        const float bb = bias[o];
        float2 a0 = unpack2(acc[i][0]);
        float2 a1 = unpack2(acc[i][1]);
        float2 a2 = unpack2(acc[i][2]);
        float2 a3 = unpack2(acc[i][3]);
        float4 rlo = make_float4(a0.x + bb, a0.y + bb, a1.x + bb, a1.y + bb);
        float4 rhi = make_float4(a2.x + bb, a2.y + bb, a3.x + bb, a3.y + bb);
        float* dst = outb + (size_t)o * HW + p0;
        *(float4*)(dst + tx * 4) = rlo;                  // always valid (p0+63 < HW)
        if (hiok) *(float4*)(dst + 64 + tx * 4) = rhi;
    }
}

// ---------------------------------------------------------------------------
__global__ __launch_bounds__(256, 2) void qkv_gemm_kernel(
    const float* __restrict__ x,
    const float* __restrict__ wq, const float* __restrict__ bq,
    const float* __restrict__ wk, const float* __restrict__ bk,
    const float* __restrict__ wv, const float* __restrict__ bv)
{
    const int bz = blockIdx.z;
    const int b  = bz / 3;
    const int m  = bz - b * 3;
    const float* W    = (m == 0) ? wq : (m == 1) ? wk : wv;
    const float* bias = (m == 0) ? bq : (m == 1) ? bk : bv;
    float* out        = ((m == 0) ? g_q : (m == 1) ? g_k : g_v) + (size_t)b * DM * HW;
    gemm128(W, bias, x + (size_t)b * DM * HW, out, blockIdx.x * 128, blockIdx.y * 128);
}

__global__ __launch_bounds__(256, 2) void oproj_gemm_kernel(
    const float* __restrict__ wo, const float* __restrict__ bo,
    float* __restrict__ out)
{
    const int b = blockIdx.z;
    gemm128(wo, bo, g_a + (size_t)b * DM * HW, out + (size_t)b * DM * HW,
            blockIdx.x * 128, blockIdx.y * 128);
}

// ---------------------------------------------------------------------------
// Windowed attention, stencil style, 2 d-slices per iteration (unchanged).
// ---------------------------------------------------------------------------
__device__ __forceinline__ void load_slice(float* dst, const float* __restrict__ src,
                                           int y0, int tid)
{
    #pragma unroll
    for (int it = 0; it < 4; it++) {
        int idx = tid + it * 224;
        int row = idx >> 6;
        int col = idx & 63;
        int gy = y0 - 3 + row;
        int gx = col - 3;
        float v = 0.f;
        if (((unsigned)gy < 56u) && ((unsigned)gx < 56u))
            v = src[gy * 56 + gx];
        dst[idx] = v;
    }
}

__global__ __launch_bounds__(224, 1) void attn_kernel()
{
    const int bh  = blockIdx.z;
    const int y0  = blockIdx.y * 8;
    const int tid = threadIdx.x;
    const int r   = tid / 28;
    const int xp  = tid - r * 28;
    const int x0  = xp * 2;
    const int p   = (y0 + r) * 56 + x0;

    const float* __restrict__ qbase = g_q + (size_t)bh * HD * HW;
    const float* __restrict__ kbase = g_k + (size_t)bh * HD * HW;
    const float* __restrict__ vbase = g_v + (size_t)bh * HD * HW;
    float*       __restrict__ abase = g_a + (size_t)bh * HD * HW;

    __shared__ __align__(16) float sk[2][2][14 * 64];

    const float scale = 0.17677669529663687f;

    float s0[NW], s1[NW];
    #pragma unroll
    for (int i = 0; i < NW; i++) { s0[i] = 0.f; s1[i] = 0.f; }

    load_slice(sk[0][0], kbase, y0, tid);
    load_slice(sk[0][1], kbase + HW, y0, tid);
    __syncthreads();

    for (int d = 0; d < HD; d += 2) {
        const int buf = (d >> 1) & 1;
        if (d + 2 < HD) {
            load_slice(sk[buf ^ 1][0], kbase + (size_t)(d + 2) * HW, y0, tid);
            load_slice(sk[buf ^ 1][1], kbase + (size_t)(d + 3) * HW, y0, tid);
        }
        float2 qa = *(const float2*)(qbase + (size_t)d * HW + p);
        float2 qb = *(const float2*)(qbase + (size_t)(d + 1) * HW + p);
        const float qa0 = qa.x * scale, qa1 = qa.y * scale;
        const float qb0 = qb.x * scale, qb1 = qb.y * scale;

        #pragma unroll
        for (int dy = 0; dy < WS; dy++) {
            float ka[8], kb[8];
            #pragma unroll
            for (int i = 0; i < 4; i++) {
                float2 ta = *(const float2*)&sk[buf][0][(r + dy) * 64 + x0 + 2 * i];
                float2 tb = *(const float2*)&sk[buf][1][(r + dy) * 64 + x0 + 2 * i];
                ka[2*i] = ta.x; ka[2*i+1] = ta.y;
                kb[2*i] = tb.x; kb[2*i+1] = tb.y;
            }
            #pragma unroll
            for (int dx = 0; dx < WS; dx++) {
                float sa0 = fmaf(qa0, ka[dx],     s0[dy * WS + dx]);
                float sa1 = fmaf(qa1, ka[dx + 1], s1[dy * WS + dx]);
                s0[dy * WS + dx] = fmaf(qb0, kb[dx],     sa0);
                s1[dy * WS + dx] = fmaf(qb1, kb[dx + 1], sa1);
            }
        }
        __syncthreads();
    }

    {
        float mx0 = s0[0], mx1 = s1[0];
        #pragma unroll
        for (int i = 1; i < NW; i++) { mx0 = fmaxf(mx0, s0[i]); mx1 = fmaxf(mx1, s1[i]); }
        float sum0 = 0.f, sum1 = 0.f;
        #pragma unroll
        for (int i = 0; i < NW; i++) {
            s0[i] = __expf(s0[i] - mx0); sum0 += s0[i];
            s1[i] = __expf(s1[i] - mx1); sum1 += s1[i];
        }
        const float inv0 = 1.f / sum0;
        const float inv1 = 1.f / sum1;
        #pragma unroll
        for (int i = 0; i < NW; i++) { s0[i] *= inv0; s1[i] *= inv1; }
    }

    load_slice(sk[0][0], vbase, y0, tid);
    load_slice(sk[0][1], vbase + HW, y0, tid);
    __syncthreads();

    for (int d = 0; d < HD; d += 2) {
        const int buf = (d >> 1) & 1;
        if (d + 2 < HD) {
            load_slice(sk[buf ^ 1][0], vbase + (size_t)(d + 2) * HW, y0, tid);
            load_slice(sk[buf ^ 1][1], vbase + (size_t)(d + 3) * HW, y0, tid);
        }
        float a0 = 0.f, a1 = 0.f, b0 = 0.f, b1 = 0.f;
        #pragma unroll
        for (int dy = 0; dy < WS; dy++) {
            float ka[8], kb[8];
            #pragma unroll
            for (int i = 0; i < 4; i++) {
                float2 ta = *(const float2*)&sk[buf][0][(r + dy) * 64 + x0 + 2 * i];
                float2 tb = *(const float2*)&sk[buf][1][(r + dy) * 64 + x0 + 2 * i];
                ka[2*i] = ta.x; ka[2*i+1] = ta.y;
                kb[2*i] = tb.x; kb[2*i+1] = tb.y;
            }
            #pragma unroll
            for (int dx = 0; dx < WS; dx++) {
                a0 = fmaf(s0[dy * WS + dx], ka[dx],     a0);
                a1 = fmaf(s1[dy * WS + dx], ka[dx + 1], a1);
                b0 = fmaf(s0[dy * WS + dx], kb[dx],     b0);
                b1 = fmaf(s1[dy * WS + dx], kb[dx + 1], b1);
            }
        }
        *(float2*)(abase + (size_t)d * HW + p)       = make_float2(a0, a1);
        *(float2*)(abase + (size_t)(d + 1) * HW + p) = make_float2(b0, b1);
        __syncthreads();
    }
}

// ---------------------------------------------------------------------------
extern "C" void kernel_launch(void* const* d_in, const int* in_sizes, int n_in,
                              void* d_out, int out_size)
{
    (void)in_sizes; (void)n_in; (void)out_size;
    const float* x  = (const float*)d_in[0];
    const float* wq = (const float*)d_in[1];
    const float* bq = (const float*)d_in[2];
    const float* wk = (const float*)d_in[3];
    const float* bk = (const float*)d_in[4];
    const float* wv = (const float*)d_in[5];
    const float* bv = (const float*)d_in[6];
    const float* wo = (const float*)d_in[7];
    const float* bo = (const float*)d_in[8];
    float* out = (float*)d_out;

    qkv_gemm_kernel<<<dim3(PXT, DM / 128, NB * 3), 256>>>(x, wq, bq, wk, bk, wv, bv);
    attn_kernel<<<dim3(1, 7, NB * NH), 224>>>();
    oproj_gemm_kernel<<<dim3(PXT, DM / 128, NB), 256>>>(wo, bo, out);
}

// round 5
// speedup vs baseline: 1.9021x; 1.0690x over previous
#include <cuda_runtime.h>
#include <cuda_bf16.h>
#include <cstdint>

// Problem constants
#define DM     256
#define HW     3136
#define NB     2
#define PTOT   (NB*HW)       // 6272 = 49*128 (fused pixel axis)
#define NH     8
#define HD     32
#define WS     7
#define NW     49

// Scratch (device globals). Fused layout: [c][P] with c = h*32+d, P = b*HW+p.
__device__ float g_q[DM * PTOT];
__device__ float g_k[DM * PTOT];
__device__ float g_v[DM * PTOT];
__device__ float g_a[DM * PTOT];
__device__ float g_part[3 * DM * PTOT];   // oproj k-split partials

// ---- packed f32x2 helpers ------------------------------------------------
typedef unsigned long long u64;
__device__ __forceinline__ u64 pack2s(float v) {
    u64 r; asm("mov.b64 %0, {%1, %1};" : "=l"(r) : "f"(v)); return r;
}
__device__ __forceinline__ void ffma2(u64& d, u64 a, u64 b) {
    asm("fma.rn.f32x2 %0, %1, %2, %0;" : "+l"(d) : "l"(a), "l"(b));
}
__device__ __forceinline__ float2 unpack2(u64 v) {
    float2 r; asm("mov.b64 {%0, %1}, %2;" : "=f"(r.x), "=f"(r.y) : "l"(v)); return r;
}

// ---------------------------------------------------------------------------
// QKV GEMM over fused P axis. grid (49, 2, 3), block 256, 128x128 tile, BK=16.
// out[o][P] = sum_c W[o][c] * x[b(P)][c][p(P)] + bias[o]
// ---------------------------------------------------------------------------
__global__ __launch_bounds__(256, 2) void qkv_gemm_kernel(
    const float* __restrict__ x,
    const float* __restrict__ wq, const float* __restrict__ bq,
    const float* __restrict__ wk, const float* __restrict__ bk,
    const float* __restrict__ wv, const float* __restrict__ bv)
{
    const int m = blockIdx.z;
    const float* __restrict__ W    = (m == 0) ? wq : (m == 1) ? wk : wv;
    const float* __restrict__ bias = (m == 0) ? bq : (m == 1) ? bk : bv;
    float* __restrict__ out        = (m == 0) ? g_q : (m == 1) ? g_k : g_v;

    const int p0 = blockIdx.x * 128;
    const int n0 = blockIdx.y * 128;

    __shared__ __align__(16) float Ws[16][128];
    __shared__ __align__(16) float Xs[16][128];

    const int tid = threadIdx.x;
    const int tx  = tid & 15;
    const int ty  = tid >> 4;

    // X loader: 8-float chunk never straddles the batch boundary (3136 % 8 == 0,
    // chunks are 8-aligned within 128-aligned tiles).
    const int px = (tid & 15) * 8;
    const int P  = p0 + px;
    const int bb = (P >= HW) ? 1 : 0;
    const float* __restrict__ xsrc = x + (size_t)bb * DM * HW + (P - bb * HW);
    const int cld = tid >> 4;

    u64 acc[8][4];
    #pragma unroll
    for (int i = 0; i < 8; i++)
        #pragma unroll
        for (int j = 0; j < 4; j++) acc[i][j] = 0ull;

    for (int k0 = 0; k0 < DM; k0 += 16) {
        {
            const int o  = tid >> 1;
            const int c0 = (tid & 1) * 8;
            #pragma unroll
            for (int cc = 0; cc < 8; cc += 4) {
                float4 w4 = *(const float4*)(W + (size_t)(n0 + o) * DM + k0 + c0 + cc);
                Ws[c0 + cc + 0][o] = w4.x;
                Ws[c0 + cc + 1][o] = w4.y;
                Ws[c0 + cc + 2][o] = w4.z;
                Ws[c0 + cc + 3][o] = w4.w;
            }
        }
        {
            const float* s = xsrc + (size_t)(k0 + cld) * HW;
            *(float4*)&Xs[cld][px]     = *(const float4*)(s);
            *(float4*)&Xs[cld][px + 4] = *(const float4*)(s + 4);
        }
        __syncthreads();
        #pragma unroll
        for (int kk = 0; kk < 16; kk++) {
            ulonglong2 xa = *(const ulonglong2*)&Xs[kk][tx * 4];
            ulonglong2 xc = *(const ulonglong2*)&Xs[kk][64 + tx * 4];
            float4 wA = *(const float4*)&Ws[kk][ty * 4];
            float4 wB = *(const float4*)&Ws[kk][64 + ty * 4];
            u64 w[8];
            w[0] = pack2s(wA.x); w[1] = pack2s(wA.y);
            w[2] = pack2s(wA.z); w[3] = pack2s(wA.w);
            w[4] = pack2s(wB.x); w[5] = pack2s(wB.y);
            w[6] = pack2s(wB.z); w[7] = pack2s(wB.w);
            #pragma unroll
            for (int i = 0; i < 8; i++) {
                ffma2(acc[i][0], w[i], xa.x);
                ffma2(acc[i][1], w[i], xa.y);
                ffma2(acc[i][2], w[i], xc.x);
                ffma2(acc[i][3], w[i], xc.y);
            }
        }
        __syncthreads();
    }

    #pragma unroll
    for (int i = 0; i < 8; i++) {
        const int o  = n0 + ((i < 4) ? (ty * 4 + i) : (64 + ty * 4 + i - 4));
        const float bv2 = bias[o];
        float2 a0 = unpack2(acc[i][0]);
        float2 a1 = unpack2(acc[i][1]);
        float2 a2 = unpack2(acc[i][2]);
        float2 a3 = unpack2(acc[i][3]);
        float* dst = out + (size_t)o * PTOT + p0;
        *(float4*)(dst + tx * 4)      = make_float4(a0.x + bv2, a0.y + bv2, a1.x + bv2, a1.y + bv2);
        *(float4*)(dst + 64 + tx * 4) = make_float4(a2.x + bv2, a2.y + bv2, a3.x + bv2, a3.y + bv2);
    }
}

// ---------------------------------------------------------------------------
// O-projection GEMM, K split 3 ways (96/80/80). grid (49, 2, 3).
// Writes partial sums (no bias) to g_part[s][o][P].
// ---------------------------------------------------------------------------
__global__ __launch_bounds__(256, 2) void oproj_gemm_kernel(const float* __restrict__ wo)
{
    const int s = blockIdx.z;
    const int kbeg = (s == 0) ? 0  : (s == 1) ? 96  : 176;
    const int kend = (s == 0) ? 96 : (s == 1) ? 176 : 256;

    const int p0 = blockIdx.x * 128;
    const int n0 = blockIdx.y * 128;

    __shared__ __align__(16) float Ws[16][128];
    __shared__ __align__(16) float Xs[16][128];

    const int tid = threadIdx.x;
    const int tx  = tid & 15;
    const int ty  = tid >> 4;
    const int px  = (tid & 15) * 8;
    const int cld = tid >> 4;

    u64 acc[8][4];
    #pragma unroll
    for (int i = 0; i < 8; i++)
        #pragma unroll
        for (int j = 0; j < 4; j++) acc[i][j] = 0ull;

    for (int k0 = kbeg; k0 < kend; k0 += 16) {
        {
            const int o  = tid >> 1;
            const int c0 = (tid & 1) * 8;
            #pragma unroll
            for (int cc = 0; cc < 8; cc += 4) {
                float4 w4 = *(const float4*)(wo + (size_t)(n0 + o) * DM + k0 + c0 + cc);
                Ws[c0 + cc + 0][o] = w4.x;
                Ws[c0 + cc + 1][o] = w4.y;
                Ws[c0 + cc + 2][o] = w4.z;
                Ws[c0 + cc + 3][o] = w4.w;
            }
        }
        {
            const float* sa = g_a + (size_t)(k0 + cld) * PTOT + p0 + px;
            *(float4*)&Xs[cld][px]     = *(const float4*)(sa);
            *(float4*)&Xs[cld][px + 4] = *(const float4*)(sa + 4);
        }
        __syncthreads();
        #pragma unroll
        for (int kk = 0; kk < 16; kk++) {
            ulonglong2 xa = *(const ulonglong2*)&Xs[kk][tx * 4];
            ulonglong2 xc = *(const ulonglong2*)&Xs[kk][64 + tx * 4];
            float4 wA = *(const float4*)&Ws[kk][ty * 4];
            float4 wB = *(const float4*)&Ws[kk][64 + ty * 4];
            u64 w[8];
            w[0] = pack2s(wA.x); w[1] = pack2s(wA.y);
            w[2] = pack2s(wA.z); w[3] = pack2s(wA.w);
            w[4] = pack2s(wB.x); w[5] = pack2s(wB.y);
            w[6] = pack2s(wB.z); w[7] = pack2s(wB.w);
            #pragma unroll
            for (int i = 0; i < 8; i++) {
                ffma2(acc[i][0], w[i], xa.x);
                ffma2(acc[i][1], w[i], xa.y);
                ffma2(acc[i][2], w[i], xc.x);
                ffma2(acc[i][3], w[i], xc.y);
            }
        }
        __syncthreads();
    }

    #pragma unroll
    for (int i = 0; i < 8; i++) {
        const int o = n0 + ((i < 4) ? (ty * 4 + i) : (64 + ty * 4 + i - 4));
        float2 a0 = unpack2(acc[i][0]);
        float2 a1 = unpack2(acc[i][1]);
        float2 a2 = unpack2(acc[i][2]);
        float2 a3 = unpack2(acc[i][3]);
        float* dst = g_part + ((size_t)s * DM + o) * PTOT + p0;
        *(float4*)(dst + tx * 4)      = make_float4(a0.x, a0.y, a1.x, a1.y);
        *(float4*)(dst + 64 + tx * 4) = make_float4(a2.x, a2.y, a3.x, a3.y);
    }
}

// Reduce partials + bias, un-fuse batch into the required [b][o][hw] layout.
__global__ __launch_bounds__(256) void oproj_reduce_kernel(
    const float* __restrict__ bo, float* __restrict__ out)
{
    const int i   = blockIdx.x * 256 + threadIdx.x;   // float4 index
    const int idx = i * 4;                            // element index in [0, DM*PTOT)
    const int o   = idx / PTOT;
    const int P   = idx - o * PTOT;
    const size_t base = (size_t)o * PTOT + P;
    float4 a = *(const float4*)&g_part[base];
    float4 b = *(const float4*)&g_part[base + (size_t)DM * PTOT];
    float4 c = *(const float4*)&g_part[base + (size_t)2 * DM * PTOT];
    const float bb = bo[o];
    float4 r = make_float4(a.x + b.x + c.x + bb, a.y + b.y + c.y + bb,
                           a.z + b.z + c.z + bb, a.w + b.w + c.w + bb);
    const int bt = (P >= HW) ? 1 : 0;                 // 3136 % 4 == 0: no straddle
    const int p  = P - bt * HW;
    *(float4*)(out + ((size_t)bt * DM + o) * HW + p) = r;
}

// ---------------------------------------------------------------------------
// Windowed attention: all 32 d-slices staged in dynamic smem per phase.
// grid (1, 7, 16), block 224 = 8 rows x 28 col-pairs. 2 syncs per phase.
// ---------------------------------------------------------------------------
#define SLICE_F 896            // 14 rows * 64 cols
#define ATTN_SMEM (HD * SLICE_F * 4)   // 114688 bytes

__device__ __forceinline__ void load_slice(float* dst, const float* __restrict__ src,
                                           int y0, int tid)
{
    #pragma unroll
    for (int it = 0; it < 4; it++) {
        int idx = tid + it * 224;
        int row = idx >> 6;
        int col = idx & 63;
        int gy = y0 - 3 + row;
        int gx = col - 3;
        float v = 0.f;
        if (((unsigned)gy < 56u) && ((unsigned)gx < 56u))
            v = src[gy * 56 + gx];
        dst[idx] = v;
    }
}

__global__ __launch_bounds__(224, 1) void attn_kernel()
{
    extern __shared__ __align__(16) float sAll[];   // [32][896]

    const int z   = blockIdx.z;           // b*NH + h
    const int b   = z >> 3;
    const int h   = z & 7;
    const int y0  = blockIdx.y * 8;
    const int tid = threadIdx.x;
    const int r   = tid / 28;
    const int xp  = tid - r * 28;
    const int x0  = xp * 2;
    const int p   = (y0 + r) * 56 + x0;

    const size_t base = (size_t)(h * HD) * PTOT + (size_t)b * HW;
    const float* __restrict__ qbase = g_q + base;
    const float* __restrict__ kbase = g_k + base;
    const float* __restrict__ vbase = g_v + base;
    float*       __restrict__ abase = g_a + base;

    const float scale = 0.17677669529663687f;

    float s0[NW], s1[NW];
    #pragma unroll
    for (int i = 0; i < NW; i++) { s0[i] = 0.f; s1[i] = 0.f; }

    // ---- Phase 1: load all K slices, then score all d without syncs ----
    for (int d = 0; d < HD; d++)
        load_slice(sAll + d * SLICE_F, kbase + (size_t)d * PTOT, y0, tid);
    __syncthreads();

    float2 qn = *(const float2*)(qbase + p);
    #pragma unroll 2
    for (int d = 0; d < HD; d++) {
        const float2 qc = qn;
        if (d + 1 < HD) qn = *(const float2*)(qbase + (size_t)(d + 1) * PTOT + p);
        const float q0 = qc.x * scale;
        const float q1 = qc.y * scale;
        const float* sl = sAll + d * SLICE_F;
        #pragma unroll
        for (int dy = 0; dy < WS; dy++) {
            float kv[8];
            #pragma unroll
            for (int i = 0; i < 4; i++) {
                float2 t = *(const float2*)&sl[(r + dy) * 64 + x0 + 2 * i];
                kv[2 * i] = t.x; kv[2 * i + 1] = t.y;
            }
            #pragma unroll
            for (int dx = 0; dx < WS; dx++) {
                s0[dy * WS + dx] = fmaf(q0, kv[dx],     s0[dy * WS + dx]);
                s1[dy * WS + dx] = fmaf(q1, kv[dx + 1], s1[dy * WS + dx]);
            }
        }
    }

    // ---- Softmax (zero scores from padding participate, matching reference) ----
    {
        float mx0 = s0[0], mx1 = s1[0];
        #pragma unroll
        for (int i = 1; i < NW; i++) { mx0 = fmaxf(mx0, s0[i]); mx1 = fmaxf(mx1, s1[i]); }
        float sum0 = 0.f, sum1 = 0.f;
        #pragma unroll
        for (int i = 0; i < NW; i++) {
            s0[i] = __expf(s0[i] - mx0); sum0 += s0[i];
            s1[i] = __expf(s1[i] - mx1); sum1 += s1[i];
        }
        const float inv0 = 1.f / sum0;
        const float inv1 = 1.f / sum1;
        #pragma unroll
        for (int i = 0; i < NW; i++) { s0[i] *= inv0; s1[i] *= inv1; }
    }

    // ---- Phase 2: load all V slices, then accumulate outputs ----
    __syncthreads();   // everyone done reading K before overwrite
    for (int d = 0; d < HD; d++)
        load_slice(sAll + d * SLICE_F, vbase + (size_t)d * PTOT, y0, tid);
    __syncthreads();

    #pragma unroll 2
    for (int d = 0; d < HD; d++) {
        const float* sl = sAll + d * SLICE_F;
        float a0 = 0.f, a1 = 0.f;
        #pragma unroll
        for (int dy = 0; dy < WS; dy++) {
            float kv[8];
            #pragma unroll
            for (int i = 0; i < 4; i++) {
                float2 t = *(const float2*)&sl[(r + dy) * 64 + x0 + 2 * i];
                kv[2 * i] = t.x; kv[2 * i + 1] = t.y;
            }
            #pragma unroll
            for (int dx = 0; dx < WS; dx++) {
                a0 = fmaf(s0[dy * WS + dx], kv[dx],     a0);
                a1 = fmaf(s1[dy * WS + dx], kv[dx + 1], a1);
            }
        }
        *(float2*)(abase + (size_t)d * PTOT + p) = make_float2(a0, a1);
    }
}

// ---------------------------------------------------------------------------
extern "C" void kernel_launch(void* const* d_in, const int* in_sizes, int n_in,
                              void* d_out, int out_size)
{
    (void)in_sizes; (void)n_in; (void)out_size;
    const float* x  = (const float*)d_in[0];
    const float* wq = (const float*)d_in[1];
    const float* bq = (const float*)d_in[2];
    const float* wk = (const float*)d_in[3];
    const float* bk = (const float*)d_in[4];
    const float* wv = (const float*)d_in[5];
    const float* bv = (const float*)d_in[6];
    const float* wo = (const float*)d_in[7];
    const float* bo = (const float*)d_in[8];
    float* out = (float*)d_out;

    static bool attr_set = false;
    if (!attr_set) {
        cudaFuncSetAttribute(attn_kernel,
                             cudaFuncAttributeMaxDynamicSharedMemorySize, ATTN_SMEM);
        attr_set = true;
    }

    qkv_gemm_kernel<<<dim3(PTOT / 128, DM / 128, 3), 256>>>(x, wq, bq, wk, bk, wv, bv);
    attn_kernel<<<dim3(1, 7, NB * NH), 224, ATTN_SMEM>>>();
    oproj_gemm_kernel<<<dim3(PTOT / 128, DM / 128, 3), 256>>>(wo);
    oproj_reduce_kernel<<<(DM * PTOT / 4) / 256, 256>>>(bo, out);
}

// round 6
// speedup vs baseline: 1.9316x; 1.0155x over previous
#include <cuda_runtime.h>
#include <cuda_bf16.h>
#include <cstdint>

// Problem constants
#define DM     256
#define HW     3136
#define NB     2
#define PTOT   (NB*HW)       // 6272 = 49*128 (fused pixel axis)
#define NH     8
#define HD     32
#define WS     7
#define NW     49

// Scratch (device globals). Fused layout: [c][P] with c = h*32+d, P = b*HW+p.
__device__ float g_q[DM * PTOT];
__device__ float g_k[DM * PTOT];
__device__ float g_v[DM * PTOT];
__device__ float g_a[DM * PTOT];
__device__ float g_part[3 * DM * PTOT];   // oproj k-split partials

// ---- packed f32x2 helpers ------------------------------------------------
typedef unsigned long long u64;
__device__ __forceinline__ u64 pack2s(float v) {
    u64 r; asm("mov.b64 %0, {%1, %1};" : "=l"(r) : "f"(v)); return r;
}
__device__ __forceinline__ void ffma2(u64& d, u64 a, u64 b) {
    asm("fma.rn.f32x2 %0, %1, %2, %0;" : "+l"(d) : "l"(a), "l"(b));
}
__device__ __forceinline__ float2 unpack2(u64 v) {
    float2 r; asm("mov.b64 {%0, %1}, %2;" : "=f"(r.x), "=f"(r.y) : "l"(v)); return r;
}

// ---------------------------------------------------------------------------
// QKV GEMM over fused P axis. grid (49, 2, 3), block 256, 128x128 tile, BK=16.
// ---------------------------------------------------------------------------
__global__ __launch_bounds__(256, 2) void qkv_gemm_kernel(
    const float* __restrict__ x,
    const float* __restrict__ wq, const float* __restrict__ bq,
    const float* __restrict__ wk, const float* __restrict__ bk,
    const float* __restrict__ wv, const float* __restrict__ bv)
{
    const int m = blockIdx.z;
    const float* __restrict__ W    = (m == 0) ? wq : (m == 1) ? wk : wv;
    const float* __restrict__ bias = (m == 0) ? bq : (m == 1) ? bk : bv;
    float* __restrict__ out        = (m == 0) ? g_q : (m == 1) ? g_k : g_v;

    const int p0 = blockIdx.x * 128;
    const int n0 = blockIdx.y * 128;

    __shared__ __align__(16) float Ws[16][128];
    __shared__ __align__(16) float Xs[16][128];

    const int tid = threadIdx.x;
    const int tx  = tid & 15;
    const int ty  = tid >> 4;

    const int px = (tid & 15) * 8;
    const int P  = p0 + px;
    const int bb = (P >= HW) ? 1 : 0;
    const float* __restrict__ xsrc = x + (size_t)bb * DM * HW + (P - bb * HW);
    const int cld = tid >> 4;

    u64 acc[8][4];
    #pragma unroll
    for (int i = 0; i < 8; i++)
        #pragma unroll
        for (int j = 0; j < 4; j++) acc[i][j] = 0ull;

    for (int k0 = 0; k0 < DM; k0 += 16) {
        {
            const int o  = tid >> 1;
            const int c0 = (tid & 1) * 8;
            #pragma unroll
            for (int cc = 0; cc < 8; cc += 4) {
                float4 w4 = *(const float4*)(W + (size_t)(n0 + o) * DM + k0 + c0 + cc);
                Ws[c0 + cc + 0][o] = w4.x;
                Ws[c0 + cc + 1][o] = w4.y;
                Ws[c0 + cc + 2][o] = w4.z;
                Ws[c0 + cc + 3][o] = w4.w;
            }
        }
        {
            const float* s = xsrc + (size_t)(k0 + cld) * HW;
            *(float4*)&Xs[cld][px]     = *(const float4*)(s);
            *(float4*)&Xs[cld][px + 4] = *(const float4*)(s + 4);
        }
        __syncthreads();
        #pragma unroll
        for (int kk = 0; kk < 16; kk++) {
            ulonglong2 xa = *(const ulonglong2*)&Xs[kk][tx * 4];
            ulonglong2 xc = *(const ulonglong2*)&Xs[kk][64 + tx * 4];
            float4 wA = *(const float4*)&Ws[kk][ty * 4];
            float4 wB = *(const float4*)&Ws[kk][64 + ty * 4];
            u64 w[8];
            w[0] = pack2s(wA.x); w[1] = pack2s(wA.y);
            w[2] = pack2s(wA.z); w[3] = pack2s(wA.w);
            w[4] = pack2s(wB.x); w[5] = pack2s(wB.y);
            w[6] = pack2s(wB.z); w[7] = pack2s(wB.w);
            #pragma unroll
            for (int i = 0; i < 8; i++) {
                ffma2(acc[i][0], w[i], xa.x);
                ffma2(acc[i][1], w[i], xa.y);
                ffma2(acc[i][2], w[i], xc.x);
                ffma2(acc[i][3], w[i], xc.y);
            }
        }
        __syncthreads();
    }

    #pragma unroll
    for (int i = 0; i < 8; i++) {
        const int o  = n0 + ((i < 4) ? (ty * 4 + i) : (64 + ty * 4 + i - 4));
        const float bv2 = bias[o];
        float2 a0 = unpack2(acc[i][0]);
        float2 a1 = unpack2(acc[i][1]);
        float2 a2 = unpack2(acc[i][2]);
        float2 a3 = unpack2(acc[i][3]);
        float* dst = out + (size_t)o * PTOT + p0;
        *(float4*)(dst + tx * 4)      = make_float4(a0.x + bv2, a0.y + bv2, a1.x + bv2, a1.y + bv2);
        *(float4*)(dst + 64 + tx * 4) = make_float4(a2.x + bv2, a2.y + bv2, a3.x + bv2, a3.y + bv2);
    }
}

// ---------------------------------------------------------------------------
// O-projection GEMM, K split 3 ways (96/80/80). grid (49, 2, 3).
// ---------------------------------------------------------------------------
__global__ __launch_bounds__(256, 2) void oproj_gemm_kernel(const float* __restrict__ wo)
{
    const int s = blockIdx.z;
    const int kbeg = (s == 0) ? 0  : (s == 1) ? 96  : 176;
    const int kend = (s == 0) ? 96 : (s == 1) ? 176 : 256;

    const int p0 = blockIdx.x * 128;
    const int n0 = blockIdx.y * 128;

    __shared__ __align__(16) float Ws[16][128];
    __shared__ __align__(16) float Xs[16][128];

    const int tid = threadIdx.x;
    const int tx  = tid & 15;
    const int ty  = tid >> 4;
    const int px  = (tid & 15) * 8;
    const int cld = tid >> 4;

    u64 acc[8][4];
    #pragma unroll
    for (int i = 0; i < 8; i++)
        #pragma unroll
        for (int j = 0; j < 4; j++) acc[i][j] = 0ull;

    for (int k0 = kbeg; k0 < kend; k0 += 16) {
        {
            const int o  = tid >> 1;
            const int c0 = (tid & 1) * 8;
            #pragma unroll
            for (int cc = 0; cc < 8; cc += 4) {
                float4 w4 = *(const float4*)(wo + (size_t)(n0 + o) * DM + k0 + c0 + cc);
                Ws[c0 + cc + 0][o] = w4.x;
                Ws[c0 + cc + 1][o] = w4.y;
                Ws[c0 + cc + 2][o] = w4.z;
                Ws[c0 + cc + 3][o] = w4.w;
            }
        }
        {
            const float* sa = g_a + (size_t)(k0 + cld) * PTOT + p0 + px;
            *(float4*)&Xs[cld][px]     = *(const float4*)(sa);
            *(float4*)&Xs[cld][px + 4] = *(const float4*)(sa + 4);
        }
        __syncthreads();
        #pragma unroll
        for (int kk = 0; kk < 16; kk++) {
            ulonglong2 xa = *(const ulonglong2*)&Xs[kk][tx * 4];
            ulonglong2 xc = *(const ulonglong2*)&Xs[kk][64 + tx * 4];
            float4 wA = *(const float4*)&Ws[kk][ty * 4];
            float4 wB = *(const float4*)&Ws[kk][64 + ty * 4];
            u64 w[8];
            w[0] = pack2s(wA.x); w[1] = pack2s(wA.y);
            w[2] = pack2s(wA.z); w[3] = pack2s(wA.w);
            w[4] = pack2s(wB.x); w[5] = pack2s(wB.y);
            w[6] = pack2s(wB.z); w[7] = pack2s(wB.w);
            #pragma unroll
            for (int i = 0; i < 8; i++) {
                ffma2(acc[i][0], w[i], xa.x);
                ffma2(acc[i][1], w[i], xa.y);
                ffma2(acc[i][2], w[i], xc.x);
                ffma2(acc[i][3], w[i], xc.y);
            }
        }
        __syncthreads();
    }

    #pragma unroll
    for (int i = 0; i < 8; i++) {
        const int o = n0 + ((i < 4) ? (ty * 4 + i) : (64 + ty * 4 + i - 4));
        float2 a0 = unpack2(acc[i][0]);
        float2 a1 = unpack2(acc[i][1]);
        float2 a2 = unpack2(acc[i][2]);
        float2 a3 = unpack2(acc[i][3]);
        float* dst = g_part + ((size_t)s * DM + o) * PTOT + p0;
        *(float4*)(dst + tx * 4)      = make_float4(a0.x, a0.y, a1.x, a1.y);
        *(float4*)(dst + 64 + tx * 4) = make_float4(a2.x, a2.y, a3.x, a3.y);
    }
}

// Reduce partials + bias, un-fuse batch into required [b][o][hw] layout.
__global__ __launch_bounds__(256) void oproj_reduce_kernel(
    const float* __restrict__ bo, float* __restrict__ out)
{
    const int i   = blockIdx.x * 256 + threadIdx.x;
    const int idx = i * 4;
    const int o   = idx / PTOT;
    const int P   = idx - o * PTOT;
    const size_t base = (size_t)o * PTOT + P;
    float4 a = *(const float4*)&g_part[base];
    float4 b = *(const float4*)&g_part[base + (size_t)DM * PTOT];
    float4 c = *(const float4*)&g_part[base + (size_t)2 * DM * PTOT];
    const float bb = bo[o];
    float4 r = make_float4(a.x + b.x + c.x + bb, a.y + b.y + c.y + bb,
                           a.z + b.z + c.z + bb, a.w + b.w + c.w + bb);
    const int bt = (P >= HW) ? 1 : 0;
    const int p  = P - bt * HW;
    *(float4*)(out + ((size_t)bt * DM + o) * HW + p) = r;
}

// ---------------------------------------------------------------------------
// Windowed attention: 4-row x 56-col tiles, 2 px/thread, double-buffered
// 2 d-slices. grid (14, 16), block 128 (112 active). smem 10 KB -> ~3 CTA/SM.
// ---------------------------------------------------------------------------
#define SROWS 10                  // 4 + 2*3 halo
#define SLICE4 (SROWS * 64)       // 640 floats

__device__ __forceinline__ void load_slice4(float* dst, const float* __restrict__ src,
                                            int y0, int tid)
{
    #pragma unroll
    for (int it = 0; it < 5; it++) {
        int idx = tid + it * 128;
        int row = idx >> 6;          // 0..9
        int col = idx & 63;
        int gy = y0 - 3 + row;
        int gx = col - 3;
        float v = 0.f;
        if (((unsigned)gy < 56u) && ((unsigned)gx < 56u))
            v = src[gy * 56 + gx];
        dst[idx] = v;
    }
}

__global__ __launch_bounds__(128) void attn_kernel()
{
    const int z   = blockIdx.y;            // b*NH + h
    const int b   = z >> 3;
    const int h   = z & 7;
    const int y0  = blockIdx.x * 4;
    const int tid = threadIdx.x;           // 0..127 (112 active)
    const bool act = (tid < 112);
    const int r   = act ? (tid / 28) : 3;  // row in tile 0..3
    const int xp  = act ? (tid - (tid / 28) * 28) : 0;
    const int x0  = xp * 2;
    const int p   = (y0 + r) * 56 + x0;

    const size_t base = (size_t)(h * HD) * PTOT + (size_t)b * HW;
    const float* __restrict__ qbase = g_q + base;
    const float* __restrict__ kbase = g_k + base;
    const float* __restrict__ vbase = g_v + base;
    float*       __restrict__ abase = g_a + base;

    __shared__ __align__(16) float sk[2][2][SLICE4];

    const float scale = 0.17677669529663687f;

    float s0[NW], s1[NW];
    #pragma unroll
    for (int i = 0; i < NW; i++) { s0[i] = 0.f; s1[i] = 0.f; }

    // ---- Phase 1: scores ----
    load_slice4(sk[0][0], kbase, y0, tid);
    load_slice4(sk[0][1], kbase + PTOT, y0, tid);
    __syncthreads();

    for (int d = 0; d < HD; d += 2) {
        const int buf = (d >> 1) & 1;
        if (d + 2 < HD) {
            load_slice4(sk[buf ^ 1][0], kbase + (size_t)(d + 2) * PTOT, y0, tid);
            load_slice4(sk[buf ^ 1][1], kbase + (size_t)(d + 3) * PTOT, y0, tid);
        }
        float2 qa = *(const float2*)(qbase + (size_t)d * PTOT + p);
        float2 qb = *(const float2*)(qbase + (size_t)(d + 1) * PTOT + p);
        const float qa0 = qa.x * scale, qa1 = qa.y * scale;
        const float qb0 = qb.x * scale, qb1 = qb.y * scale;

        #pragma unroll
        for (int dy = 0; dy < WS; dy++) {
            float ka[8], kb[8];
            #pragma unroll
            for (int i = 0; i < 4; i++) {
                float2 ta = *(const float2*)&sk[buf][0][(r + dy) * 64 + x0 + 2 * i];
                float2 tb = *(const float2*)&sk[buf][1][(r + dy) * 64 + x0 + 2 * i];
                ka[2*i] = ta.x; ka[2*i+1] = ta.y;
                kb[2*i] = tb.x; kb[2*i+1] = tb.y;
            }
            #pragma unroll
            for (int dx = 0; dx < WS; dx++) {
                float sa0 = fmaf(qa0, ka[dx],     s0[dy * WS + dx]);
                float sa1 = fmaf(qa1, ka[dx + 1], s1[dy * WS + dx]);
                s0[dy * WS + dx] = fmaf(qb0, kb[dx],     sa0);
                s1[dy * WS + dx] = fmaf(qb1, kb[dx + 1], sa1);
            }
        }
        __syncthreads();
    }

    // ---- Softmax ----
    {
        float mx0 = s0[0], mx1 = s1[0];
        #pragma unroll
        for (int i = 1; i < NW; i++) { mx0 = fmaxf(mx0, s0[i]); mx1 = fmaxf(mx1, s1[i]); }
        float sum0 = 0.f, sum1 = 0.f;
        #pragma unroll
        for (int i = 0; i < NW; i++) {
            s0[i] = __expf(s0[i] - mx0); sum0 += s0[i];
            s1[i] = __expf(s1[i] - mx1); sum1 += s1[i];
        }
        const float inv0 = 1.f / sum0;
        const float inv1 = 1.f / sum1;
        #pragma unroll
        for (int i = 0; i < NW; i++) { s0[i] *= inv0; s1[i] *= inv1; }
    }

    // ---- Phase 2: output ----
    load_slice4(sk[0][0], vbase, y0, tid);
    load_slice4(sk[0][1], vbase + PTOT, y0, tid);
    __syncthreads();

    for (int d = 0; d < HD; d += 2) {
        const int buf = (d >> 1) & 1;
        if (d + 2 < HD) {
            load_slice4(sk[buf ^ 1][0], vbase + (size_t)(d + 2) * PTOT, y0, tid);
            load_slice4(sk[buf ^ 1][1], vbase + (size_t)(d + 3) * PTOT, y0, tid);
        }
        float a0 = 0.f, a1 = 0.f, b0 = 0.f, b1 = 0.f;
        #pragma unroll
        for (int dy = 0; dy < WS; dy++) {
            float ka[8], kb[8];
            #pragma unroll
            for (int i = 0; i < 4; i++) {
                float2 ta = *(const float2*)&sk[buf][0][(r + dy) * 64 + x0 + 2 * i];
                float2 tb = *(const float2*)&sk[buf][1][(r + dy) * 64 + x0 + 2 * i];
                ka[2*i] = ta.x; ka[2*i+1] = ta.y;
                kb[2*i] = tb.x; kb[2*i+1] = tb.y;
            }
            #pragma unroll
            for (int dx = 0; dx < WS; dx++) {
                a0 = fmaf(s0[dy * WS + dx], ka[dx],     a0);
                a1 = fmaf(s1[dy * WS + dx], ka[dx + 1], a1);
                b0 = fmaf(s0[dy * WS + dx], kb[dx],     b0);
                b1 = fmaf(s1[dy * WS + dx], kb[dx + 1], b1);
            }
        }
        if (act) {
            *(float2*)(abase + (size_t)d * PTOT + p)       = make_float2(a0, a1);
            *(float2*)(abase + (size_t)(d + 1) * PTOT + p) = make_float2(b0, b1);
        }
        __syncthreads();
    }
}

// ---------------------------------------------------------------------------
extern "C" void kernel_launch(void* const* d_in, const int* in_sizes, int n_in,
                              void* d_out, int out_size)
{
    (void)in_sizes; (void)n_in; (void)out_size;
    const float* x  = (const float*)d_in[0];
    const float* wq = (const float*)d_in[1];
    const float* bq = (const float*)d_in[2];
    const float* wk = (const float*)d_in[3];
    const float* bk = (const float*)d_in[4];
    const float* wv = (const float*)d_in[5];
    const float* bv = (const float*)d_in[6];
    const float* wo = (const float*)d_in[7];
    const float* bo = (const float*)d_in[8];
    float* out = (float*)d_out;

    qkv_gemm_kernel<<<dim3(PTOT / 128, DM / 128, 3), 256>>>(x, wq, bq, wk, bk, wv, bv);
    attn_kernel<<<dim3(14, NB * NH), 128>>>();
    oproj_gemm_kernel<<<dim3(PTOT / 128, DM / 128, 3), 256>>>(wo);
    oproj_reduce_kernel<<<(DM * PTOT / 4) / 256, 256>>>(bo, out);
}